// round 1
// baseline (speedup 1.0000x reference)
#include <cuda_runtime.h>

#define GH 31
#define GW 51
#define NPTS (GH*GW)          // 1581
#define PADC 30
#define KS 61
#define NBOX 20
#define BATCH 16
#define OH 1080
#define OW 1920

// Scratch (no allocations allowed): per-batch interpolated grids.
__device__ float g_xout[BATCH * OW];
__device__ float g_yout[BATCH * OH];

// One block per batch element. Computes the whole KDE -> conv -> grid ->
// 1D-interp pipeline for that batch. All tiny; lives in shared memory.
__global__ __launch_bounds__(256) void sal_kernel(const float* __restrict__ bboxes) {
    const int b   = blockIdx.x;
    const int tid = threadIdx.x;

    __shared__ float S[NPTS];       // accumulated saliency (vec layout: [w*31+h])
    __shared__ float tmp[NPTS];     // per-bbox unnormalized saliency
    __shared__ float red[256];      // reduction scratch
    __shared__ float xsal[GW];
    __shared__ float ysal[GH];
    __shared__ float filt[KS];
    __shared__ float xgrid[GW];
    __shared__ float ygrid[GH];

    // Gaussian filter (reference computes in float64 then casts).
    if (tid < KS) {
        double x = (double)tid - (double)PADC;
        filt[tid] = (float)exp(-4.0 * 0.693147180559945309 * x * x / (13.0 * 13.0));
    }
    for (int i = tid; i < NPTS; i += 256) S[i] = 0.0f;
    __syncthreads();

    const float* bb = bboxes + b * NBOX * 4;

    for (int n = 0; n < NBOX; n++) {
        const float x1 = bb[n*4+0], y1 = bb[n*4+1], x2 = bb[n*4+2], y2 = bb[n*4+3];
        const float w  = x2 - x1, h = y2 - y1;
        const float cx = x1 + 0.5f * w, cy = y1 + 0.5f * h;
        const float invw = 1.0f / w, invh = 1.0f / h;

        float local = 0.0f;
        for (int i = tid; i < NPTS; i += 256) {
            const int wi = i / GH;       // point index = w*GH + h
            const int hi = i - wi * GH;
            const float gx = (float)wi * (1920.0f / 50.0f);
            const float gy = (float)hi * (1080.0f / 30.0f);
            const float dx = cx - gx, dy = cy - gy;
            const float dist = dx * dx * invw + dy * dy * invh;
            const float e = expf(-0.5f * dist);
            tmp[i] = e;
            local += e;
        }
        red[tid] = local;
        __syncthreads();
        #pragma unroll
        for (int s = 128; s > 0; s >>= 1) {
            if (tid < s) red[tid] += red[tid + s];
            __syncthreads();
        }
        const float inv = 1.0f / (1e-5f + red[0]);
        __syncthreads();
        for (int i = tid; i < NPTS; i += 256) S[i] += tmp[i] * inv;
        __syncthreads();
    }

    // + uniform bias summed over all bboxes. Global normalization by
    // S.sum() cancels exactly in ox/wx and oy/wy, so it is skipped.
    const float bias = (float)NBOX * (1.0f / (float)(KS * KS));
    for (int i = tid; i < NPTS; i += 256) S[i] += bias;
    __syncthreads();

    // Marginals. vec layout: sal2d[h][w] = S[w*GH + h].
    if (tid < GW) {
        float s = 0.0f;
        #pragma unroll
        for (int h = 0; h < GH; h++) s += S[tid * GH + h];
        xsal[tid] = s;
    }
    if (tid >= 64 && tid < 64 + GH) {
        const int hh = tid - 64;
        float s = 0.0f;
        #pragma unroll
        for (int w = 0; w < GW; w++) s += S[w * GH + hh];
        ysal[hh] = s;
    }
    __syncthreads();

    // 61-tap valid convs on reflect-padded marginals; grid = clip(o/w*2-1).
    if (tid < GW) {
        const int o = tid;
        float ws = 0.0f, os = 0.0f;
        #pragma unroll 1
        for (int k = 0; k < KS; k++) {
            const int j = o + k - PADC;                        // unpadded index
            const int idx = j < 0 ? -j : (j > GW - 1 ? 2 * (GW - 1) - j : j);
            const float v = xsal[idx];
            const float P = (float)(o + k - PADC) / (float)(GW - 1);
            const float f = filt[k];
            ws += v * f;
            os += P * v * f;
        }
        float g = os / ws * 2.0f - 1.0f;
        xgrid[o] = fminf(1.0f, fmaxf(-1.0f, g));
    }
    if (tid >= 64 && tid < 64 + GH) {
        const int o = tid - 64;
        float ws = 0.0f, os = 0.0f;
        #pragma unroll 1
        for (int k = 0; k < KS; k++) {
            const int j = o + k - PADC;
            const int idx = j < 0 ? -j : (j > GH - 1 ? 2 * (GH - 1) - j : j);
            const float v = ysal[idx];
            const float P = (float)(o + k - PADC) / (float)(GH - 1);
            const float f = filt[k];
            ws += v * f;
            os += P * v * f;
        }
        float g = os / ws * 2.0f - 1.0f;
        ygrid[o] = fminf(1.0f, fmaxf(-1.0f, g));
    }
    __syncthreads();

    // Align-corners 1D bilinear interp to the output axes.
    for (int ox = tid; ox < OW; ox += 256) {
        const float pos = (float)ox * ((float)(GW - 1) / (float)(OW - 1));
        int x0 = (int)floorf(pos);
        if (x0 > GW - 1) x0 = GW - 1;
        const float t = pos - (float)x0;
        const int x1 = min(x0 + 1, GW - 1);
        g_xout[b * OW + ox] = xgrid[x0] * (1.0f - t) + xgrid[x1] * t;
    }
    for (int oy = tid; oy < OH; oy += 256) {
        const float pos = (float)oy * ((float)(GH - 1) / (float)(OH - 1));
        int y0 = (int)floorf(pos);
        if (y0 > GH - 1) y0 = GH - 1;
        const float t = pos - (float)y0;
        const int y1 = min(y0 + 1, GH - 1);
        g_yout[b * OH + oy] = ygrid[y0] * (1.0f - t) + ygrid[y1] * t;
    }
}

// Streaming writer: out[b][oy][ox][{0,1}] = {xout[b][ox], yout[b][oy]}.
// One float4 (= 2 pixels) per thread; pure store bandwidth.
__global__ __launch_bounds__(256) void fill_kernel(float4* __restrict__ out) {
    const int b  = blockIdx.z;
    const int oy = blockIdx.y;
    const int t  = blockIdx.x * blockDim.x + threadIdx.x;   // float4 index in row
    if (t >= OW / 2) return;
    const float yv = g_yout[b * OH + oy];
    const float2 xv = reinterpret_cast<const float2*>(g_xout + b * OW)[t];
    out[((size_t)(b * OH + oy)) * (OW / 2) + t] = make_float4(xv.x, yv, xv.y, yv);
}

extern "C" void kernel_launch(void* const* d_in, const int* in_sizes, int n_in,
                              void* d_out, int out_size) {
    // d_in[0] = imgs (unused: only its batch dim matters, fixed at 16)
    // d_in[1] = gt_bboxes [16, 20, 4] float32
    const float* bboxes = (const float*)d_in[1];

    sal_kernel<<<BATCH, 256>>>(bboxes);
    fill_kernel<<<dim3((OW / 2 + 255) / 256, OH, BATCH), 256>>>((float4*)d_out);
}

// round 2
// speedup vs baseline: 1.6174x; 1.6174x over previous
#include <cuda_runtime.h>

#define GH 31
#define GW 51
#define NPTS (GH*GW)          // 1581
#define PADC 30
#define KS 61
#define NBOX 20
#define BATCH 16
#define OH 1080
#define OW 1920
#define NW 8                  // warps per sal block
#define EPT 50                // exp points per lane: 50*32 >= 1581
#define RPB 8                 // output rows per fill block

// Scratch (no allocations allowed): per-batch interpolated grids.
__device__ float g_xout[BATCH * OW];
__device__ float g_yout[BATCH * OH];

// One block per batch element. Warp-per-bbox KDE accumulation (no block
// syncs in the main loop), then marginals -> 61-tap conv -> 1D interp.
__global__ __launch_bounds__(256) void sal_kernel(const float* __restrict__ bboxes) {
    const int b    = blockIdx.x;
    const int tid  = threadIdx.x;
    const int lane = tid & 31;
    const int w    = tid >> 5;

    __shared__ float Spart[NW][NPTS];   // per-warp partial saliency (~50.6 KB)
    __shared__ float S[NPTS];           // combined saliency
    __shared__ float xsal[GW];
    __shared__ float ysal[GH];
    __shared__ float filt[KS];
    __shared__ float xgrid[GW];
    __shared__ float ygrid[GH];

    // Gaussian filter (reference computes in float64 then casts).
    if (tid < KS) {
        double x = (double)tid - (double)PADC;
        filt[tid] = (float)exp(-4.0 * 0.693147180559945309 * x * x / (13.0 * 13.0));
    }
    for (int i = lane; i < NPTS; i += 32) Spart[w][i] = 0.0f;
    __syncwarp();

    const float* bb = bboxes + b * NBOX * 4;

    // Each warp processes boxes n = w, w+8, w+16 independently.
    for (int n = w; n < NBOX; n += NW) {
        const float x1 = bb[n*4+0], y1 = bb[n*4+1], x2 = bb[n*4+2], y2 = bb[n*4+3];
        const float bw = x2 - x1, bh = y2 - y1;
        const float cx = x1 + 0.5f * bw, cy = y1 + 0.5f * bh;
        const float invw = 1.0f / bw, invh = 1.0f / bh;

        float e[EPT];
        float lsum = 0.0f;
        #pragma unroll
        for (int j = 0; j < EPT; j++) {
            const int i = lane + 32 * j;
            float val = 0.0f;
            if (i < NPTS) {
                const int wi = i / GH;       // point index = w*GH + h
                const int hi = i - wi * GH;
                const float gx = (float)wi * (1920.0f / 50.0f);
                const float gy = (float)hi * (1080.0f / 30.0f);
                const float dx = cx - gx, dy = cy - gy;
                val = expf(-0.5f * (dx * dx * invw + dy * dy * invh));
            }
            e[j] = val;
            lsum += val;
        }
        // warp all-reduce
        #pragma unroll
        for (int s = 16; s > 0; s >>= 1) lsum += __shfl_xor_sync(0xffffffffu, lsum, s);
        const float inv = 1.0f / (1e-5f + lsum);
        #pragma unroll
        for (int j = 0; j < EPT; j++) {
            const int i = lane + 32 * j;
            if (i < NPTS) Spart[w][i] += e[j] * inv;
        }
    }
    __syncthreads();

    // Combine partials + uniform bias (global S.sum() normalization cancels
    // exactly in ox/wx and oy/wy, so it is skipped).
    const float bias = (float)NBOX * (1.0f / (float)(KS * KS));
    for (int i = tid; i < NPTS; i += 256) {
        float s = bias;
        #pragma unroll
        for (int ww = 0; ww < NW; ww++) s += Spart[ww][i];
        S[i] = s;
    }
    __syncthreads();

    // Marginals. vec layout: sal2d[h][w] = S[w*GH + h].
    if (tid < GW) {
        float s = 0.0f;
        #pragma unroll
        for (int h = 0; h < GH; h++) s += S[tid * GH + h];
        xsal[tid] = s;
    }
    if (tid >= 64 && tid < 64 + GH) {
        const int hh = tid - 64;
        float s = 0.0f;
        #pragma unroll
        for (int ww = 0; ww < GW; ww++) s += S[ww * GH + hh];
        ysal[hh] = s;
    }
    __syncthreads();

    // 61-tap valid convs on reflect-padded marginals; grid = clip(o/w*2-1).
    if (tid < GW) {
        const int o = tid;
        float ws = 0.0f, os = 0.0f;
        #pragma unroll
        for (int k = 0; k < KS; k++) {
            const int j = o + k - PADC;                        // unpadded index
            const int idx = j < 0 ? -j : (j > GW - 1 ? 2 * (GW - 1) - j : j);
            const float v = xsal[idx];
            const float P = (float)(o + k - PADC) / (float)(GW - 1);
            const float f = filt[k];
            ws += v * f;
            os += P * v * f;
        }
        float g = os / ws * 2.0f - 1.0f;
        xgrid[o] = fminf(1.0f, fmaxf(-1.0f, g));
    }
    if (tid >= 64 && tid < 64 + GH) {
        const int o = tid - 64;
        float ws = 0.0f, os = 0.0f;
        #pragma unroll
        for (int k = 0; k < KS; k++) {
            const int j = o + k - PADC;
            const int idx = j < 0 ? -j : (j > GH - 1 ? 2 * (GH - 1) - j : j);
            const float v = ysal[idx];
            const float P = (float)(o + k - PADC) / (float)(GH - 1);
            const float f = filt[k];
            ws += v * f;
            os += P * v * f;
        }
        float g = os / ws * 2.0f - 1.0f;
        ygrid[o] = fminf(1.0f, fmaxf(-1.0f, g));
    }
    __syncthreads();

    // Align-corners 1D bilinear interp to the output axes.
    for (int ox = tid; ox < OW; ox += 256) {
        const float pos = (float)ox * ((float)(GW - 1) / (float)(OW - 1));
        int x0 = (int)floorf(pos);
        if (x0 > GW - 1) x0 = GW - 1;
        const float t = pos - (float)x0;
        const int x1 = min(x0 + 1, GW - 1);
        g_xout[b * OW + ox] = xgrid[x0] * (1.0f - t) + xgrid[x1] * t;
    }
    for (int oy = tid; oy < OH; oy += 256) {
        const float pos = (float)oy * ((float)(GH - 1) / (float)(OH - 1));
        int y0 = (int)floorf(pos);
        if (y0 > GH - 1) y0 = GH - 1;
        const float t = pos - (float)y0;
        const int y1 = min(y0 + 1, GH - 1);
        g_yout[b * OH + oy] = ygrid[y0] * (1.0f - t) + ygrid[y1] * t;
    }
}

// Streaming writer: out[b][oy][ox][{0,1}] = {xout[b][ox], yout[b][oy]}.
// One block per (batch, 8-row tile). Each thread keeps 4 float2 x-values in
// registers (reused across 8 rows) and issues 32 independent streaming
// STG.128 -> deep store MLP, few blocks, pure write bandwidth.
__global__ __launch_bounds__(256) void fill_kernel(float4* __restrict__ out) {
    const int b  = blockIdx.z;
    const int r0 = blockIdx.y * RPB;
    const int t  = threadIdx.x;

    const float2* xrow = reinterpret_cast<const float2*>(g_xout + b * OW);
    const float2 xv0 = xrow[t];
    const float2 xv1 = xrow[t + 256];
    const float2 xv2 = xrow[t + 512];
    const bool   has3 = (t < OW / 2 - 768);            // 960-768 = 192
    const float2 xv3 = has3 ? xrow[t + 768] : make_float2(0.f, 0.f);

    float yv[RPB];
    #pragma unroll
    for (int r = 0; r < RPB; r++) yv[r] = g_yout[b * OH + r0 + r];

    float4* base = out + (size_t)(b * OH + r0) * (OW / 2);
    #pragma unroll
    for (int r = 0; r < RPB; r++) {
        float4* row = base + (size_t)r * (OW / 2);
        const float y = yv[r];
        __stcs(row + t,       make_float4(xv0.x, y, xv0.y, y));
        __stcs(row + t + 256, make_float4(xv1.x, y, xv1.y, y));
        __stcs(row + t + 512, make_float4(xv2.x, y, xv2.y, y));
        if (has3)
            __stcs(row + t + 768, make_float4(xv3.x, y, xv3.y, y));
    }
}

extern "C" void kernel_launch(void* const* d_in, const int* in_sizes, int n_in,
                              void* d_out, int out_size) {
    // d_in[0] = imgs (unused: only its batch dim matters, fixed at 16)
    // d_in[1] = gt_bboxes [16, 20, 4] float32
    const float* bboxes = (const float*)d_in[1];

    sal_kernel<<<BATCH, 256>>>(bboxes);
    fill_kernel<<<dim3(1, OH / RPB, BATCH), 256>>>((float4*)d_out);
}